// round 5
// baseline (speedup 1.0000x reference)
#include <cuda_runtime.h>

// ---------------------------------------------------------------------------
// SSIM loss, fused single pass, single kernel, packed-f32x2 math.
// Tile: 64 (x) x 16 (y), 256 threads, 4 blocks/SM (49.1 KB smem).
// Stage 0: raw img1/img2 tile (5-px zero-padded halo) -> smem.
// Stage A: horizontal 11-tap blur; fields packed (a,b) and (a^2,b^2) via
//          fma.rn.f32x2 (FFMA2, 2 FMA/slot), ab scalar.  H stored
//          field-interleaved: float2 planes H_ab, H_sq + float plane H_x.
// Stage B: vertical 11-tap blur on packed planes (LDS.64 x2 + LDS.32 per
//          tap) + ssim epilogue; 4-row runs, 256 jobs = 256 threads.
// Reduce:  warp shuffle -> block -> atomicAdd(double); counter-elected last
//          block writes 1 - mean and resets accumulators (replay-safe).
// ---------------------------------------------------------------------------

#define NTHREADS 256
#define TX 64
#define TY 16
#define RROWS 26          // TY + 10
#define RCOLS 74          // TX + 10
#define RSTRIDE 76        // raw row stride (floats), multiple of 4
#define IMG 1024
#define NBLOCKS (16 * 64 * 32)

// smem: raw 2*26*76*4 = 15808 B; H_ab 26*64*8 = 13312; H_sq 13312;
//       H_x 26*64*4 = 6656; wsum 32  -> 49120 B total.
#define RAW_FLOATS (2 * RROWS * RSTRIDE)
#define HAB_U64S   (RROWS * TX)
#define HX_FLOATS  (RROWS * TX)
#define SMEM_BYTES (RAW_FLOATS * 4 + 2 * HAB_U64S * 8 + HX_FLOATS * 4 + 32)

typedef unsigned long long ull;

#define W0 0.00102838f
#define W1 0.00759875f
#define W2 0.03600077f
#define W3 0.10936069f
#define W4 0.21300553f
#define W5 0.26601172f

static __device__ __forceinline__ float Wt(int t) {
    constexpr float w[11] = {W0, W1, W2, W3, W4, W5, W4, W3, W2, W1, W0};
    return w[t];
}

// Broadcast weight pairs (w,w) in constant memory; uniform accesses promote
// to the uniform-const path (UR), keeping the regular RF free.
__constant__ float2 WB[11] = {
    {W0, W0}, {W1, W1}, {W2, W2}, {W3, W3}, {W4, W4}, {W5, W5},
    {W4, W4}, {W3, W3}, {W2, W2}, {W1, W1}, {W0, W0}};

static __device__ __forceinline__ ull wb(int t) {
    return *reinterpret_cast<const ull*>(&WB[t]);
}
static __device__ __forceinline__ ull packf2(float x, float y) {
    ull r; asm("mov.b64 %0, {%1, %2};" : "=l"(r) : "f"(x), "f"(y)); return r;
}
static __device__ __forceinline__ void unpackf2(float& x, float& y, ull v) {
    asm("mov.b64 {%0, %1}, %2;" : "=f"(x), "=f"(y) : "l"(v));
}
static __device__ __forceinline__ ull f2mul(ull a, ull b) {
    ull r; asm("mul.rn.f32x2 %0, %1, %2;" : "=l"(r) : "l"(a), "l"(b)); return r;
}
static __device__ __forceinline__ ull f2fma(ull a, ull b, ull c) {
    ull r; asm("fma.rn.f32x2 %0, %1, %2, %3;"
               : "=l"(r) : "l"(a), "l"(b), "l"(c));
    return r;
}

__device__ double g_acc = 0.0;
__device__ unsigned g_count = 0u;

__global__ __launch_bounds__(NTHREADS, 4)
void ssim_main(const float* __restrict__ img1, const float* __restrict__ img2,
               float* __restrict__ out) {
    extern __shared__ float smem[];
    float* r1   = smem;                                   // [RROWS][RSTRIDE]
    float* r2   = smem + RROWS * RSTRIDE;                 // [RROWS][RSTRIDE]
    ull*   Hab  = reinterpret_cast<ull*>(smem + RAW_FLOATS);        // [RROWS][TX]
    ull*   Hsq  = Hab + HAB_U64S;                                   // [RROWS][TX]
    float* Hx   = reinterpret_cast<float*>(Hsq + HAB_U64S);         // [RROWS][TX]
    float* wsum = Hx + HX_FLOATS;                                   // [8]

    const float C1f = 0.0004f;   // (0.01*2)^2
    const float C2f = 0.0036f;   // (0.03*2)^2

    const int tid = threadIdx.x;
    const int tx0 = blockIdx.x * TX;
    const int ty0 = blockIdx.y * TY;
    const size_t base = (size_t)blockIdx.z * (size_t)(IMG * IMG);

    // -------- Stage 0: raw tile load (zero-pad outside image) --------------
    #pragma unroll
    for (int idx = tid; idx < RROWS * RCOLS; idx += NTHREADS) {
        const int r = idx / RCOLS;
        const int c = idx - r * RCOLS;
        const int gy = ty0 + r - 5;
        const int gx = tx0 + c - 5;
        float a = 0.f, b = 0.f;
        if ((unsigned)gy < (unsigned)IMG && (unsigned)gx < (unsigned)IMG) {
            const size_t o = base + (size_t)gy * IMG + (size_t)gx;
            a = __ldg(img1 + o);
            b = __ldg(img2 + o);
        }
        r1[r * RSTRIDE + c] = a;
        r2[r * RSTRIDE + c] = b;
    }
    __syncthreads();

    // -------- Stage A: horizontal blur, packed fields ----------------------
    // 26 rows x 8 column-groups of 8 = 208 jobs; threads 208..255 idle.
    if (tid < RROWS * 8) {
        const int r  = tid >> 3;
        const int c0 = (tid & 7) * 8;
        const float4* p1 = reinterpret_cast<const float4*>(r1 + r * RSTRIDE + c0);
        const float4* p2 = reinterpret_cast<const float4*>(r2 + r * RSTRIDE + c0);

        ull acc_ab[8], acc_sq[8];
        float acc_x[8];
        #pragma unroll
        for (int i = 0; i < 8; i++) { acc_ab[i] = 0ull; acc_sq[i] = 0ull; acc_x[i] = 0.f; }

        #pragma unroll
        for (int q = 0; q < 5; q++) {
            const float4 v1 = p1[q];
            const float4 v2 = p2[q];
            const float a4[4] = {v1.x, v1.y, v1.z, v1.w};
            const float b4[4] = {v2.x, v2.y, v2.z, v2.w};
            #pragma unroll
            for (int i = 0; i < 4; i++) {
                const int k = 4 * q + i;
                if (k < 18) {
                    const float a = a4[i];
                    const float b = b4[i];
                    const ull pab = packf2(a, b);
                    const ull psq = f2mul(pab, pab);
                    const float ab = a * b;
                    #pragma unroll
                    for (int jj = 0; jj < 8; jj++) {
                        const int t = k - jj;
                        if (t >= 0 && t <= 10) {
                            acc_ab[jj] = f2fma(wb(t), pab, acc_ab[jj]);
                            acc_sq[jj] = f2fma(wb(t), psq, acc_sq[jj]);
                            acc_x[jj] += Wt(t) * ab;
                        }
                    }
                }
            }
        }
        #pragma unroll
        for (int jj = 0; jj < 8; jj++) {
            const int o = r * TX + c0 + jj;
            Hab[o] = acc_ab[jj];
            Hsq[o] = acc_sq[jj];
            Hx[o]  = acc_x[jj];
        }
    }
    __syncthreads();

    // -------- Stage B: vertical blur + ssim, 4 rows per thread -------------
    float lsum = 0.f;
    {
        const int c  = tid & (TX - 1);          // output column 0..63
        const int g4 = (tid >> 6) * 4;          // first output row
        ull v01[4], v23[4];
        float v4[4];
        #pragma unroll
        for (int i = 0; i < 4; i++) { v01[i] = 0ull; v23[i] = 0ull; v4[i] = 0.f; }

        #pragma unroll
        for (int k = 0; k < 14; k++) {
            const int o = (g4 + k) * TX + c;
            const ull hab = Hab[o];
            const ull hsq = Hsq[o];
            const float hx = Hx[o];
            #pragma unroll
            for (int jj = 0; jj < 4; jj++) {
                const int t = k - jj;
                if (t >= 0 && t <= 10) {
                    v01[jj] = f2fma(wb(t), hab, v01[jj]);
                    v23[jj] = f2fma(wb(t), hsq, v23[jj]);
                    v4[jj] += Wt(t) * hx;
                }
            }
        }

        #pragma unroll
        for (int jj = 0; jj < 4; jj++) {
            float mu1, mu2, q1, q2;
            unpackf2(mu1, mu2, v01[jj]);
            unpackf2(q1,  q2,  v23[jj]);
            const float mu12 = mu1 * mu2;
            const float mu1s = mu1 * mu1;
            const float mu2s = mu2 * mu2;
            const float s1  = q1 - mu1s;
            const float s2  = q2 - mu2s;
            const float s12 = v4[jj] - mu12;
            const float num = (2.f * mu12 + C1f) * (2.f * s12 + C2f);
            const float den = (mu1s + mu2s + C1f) * (s1 + s2 + C2f);
            lsum += __fdividef(num, den);
        }
    }

    // -------- Reduction ----------------------------------------------------
    #pragma unroll
    for (int o = 16; o > 0; o >>= 1)
        lsum += __shfl_xor_sync(0xffffffffu, lsum, o);
    if ((tid & 31) == 0) wsum[tid >> 5] = lsum;
    __syncthreads();
    if (tid == 0) {
        float bs = 0.f;
        #pragma unroll
        for (int w = 0; w < 8; w++) bs += wsum[w];
        atomicAdd(&g_acc, (double)bs);
        __threadfence();
        const unsigned old = atomicAdd(&g_count, 1u);
        if (old == NBLOCKS - 1) {
            const double s = *((volatile double*)&g_acc);
            out[0] = (float)(1.0 - s * (1.0 / 33554432.0));  // 32*1024*1024
            *((volatile double*)&g_acc) = 0.0;
            __threadfence();
            atomicExch(&g_count, 0u);
        }
    }
}

extern "C" void kernel_launch(void* const* d_in, const int* in_sizes, int n_in,
                              void* d_out, int out_size) {
    (void)in_sizes; (void)n_in; (void)out_size;
    const float* img1 = (const float*)d_in[0];
    const float* img2 = (const float*)d_in[1];
    float* out = (float*)d_out;

    static int smem_set = 0;
    if (!smem_set) {
        cudaFuncSetAttribute(ssim_main,
                             cudaFuncAttributeMaxDynamicSharedMemorySize,
                             SMEM_BYTES);
        smem_set = 1;
    }

    dim3 grid(IMG / TX, IMG / TY, 32);   // 16 x 64 x 32 = 32768 blocks
    ssim_main<<<grid, NTHREADS, SMEM_BYTES>>>(img1, img2, out);
}

// round 7
// speedup vs baseline: 1.0494x; 1.0494x over previous
#include <cuda_runtime.h>

// ---------------------------------------------------------------------------
// SSIM loss, fused strip kernel (rolling horizontal-blur buffer).
// Block owns a 64 (x) x 128 (y) strip, processed as 8 chunks of 16 rows.
// Chunk 0: load 26 raw rows, compute all 26 H rows (8-col runs, 208 jobs).
// Chunk i: copy H rows 16..25 -> 0..9 (10-row overlap carried), load 16 new
//          raw rows, compute 16 new H rows (4-col runs, 256 jobs = 256 thr).
// Stage B per chunk: vertical 11-tap blur + ssim epilogue, 4-row runs.
// H layout: 5 scalar planes [RROWS][HSTRIDE] (conflict-free stage-B LDS).
// Weights are compile-time immediates -> FFMA-imm (rt_SMSP=1).
// Reduce: warp shuffle -> block -> atomicAdd(double); counter-elected last
//         block writes 1 - mean and resets accumulators (replay-safe).
// ---------------------------------------------------------------------------

#define NTHREADS 256
#define TX 64
#define TY 16            // rows per chunk
#define NCHUNK 8         // chunks per strip
#define SY (TY * NCHUNK) // 128 rows per strip
#define RROWS 26         // TY + 10
#define RCOLS 74         // TX + 10
#define RSTRIDE 76       // raw row stride (floats), multiple of 4
#define HSTRIDE 68       // H row stride (floats), multiple of 4
#define IMG 1024
#define NBLOCKS (16 * 8 * 32)

#define SMEM_FLOATS (2 * RROWS * RSTRIDE + 5 * RROWS * HSTRIDE + 8)
#define SMEM_BYTES (SMEM_FLOATS * 4)   // 51,232 B -> 4 blocks/SM

static __device__ __forceinline__ float Wt(int t) {
    // Gaussian, WIN=11, SIGMA=1.5, normalized; compile-time constants so
    // ptxas emits FFMA-imm (rt_SMSP=1, 2x tput vs 3-reg FFMA).
    constexpr float w[6] = {0.00102838f, 0.00759875f, 0.03600077f,
                            0.10936069f, 0.21300553f, 0.26601172f};
    return (t < 6) ? w[t] : w[10 - t];
}

__device__ double g_acc = 0.0;
__device__ unsigned g_count = 0u;

__global__ __launch_bounds__(NTHREADS, 4)
void ssim_main(const float* __restrict__ img1, const float* __restrict__ img2,
               float* __restrict__ out) {
    extern __shared__ float smem[];
    float* r1   = smem;                                // [RROWS][RSTRIDE]
    float* r2   = smem + RROWS * RSTRIDE;              // [RROWS][RSTRIDE]
    float* H    = smem + 2 * RROWS * RSTRIDE;          // [5][RROWS][HSTRIDE]
    float* wsum = H + 5 * RROWS * HSTRIDE;             // [8]

    const float C1f = 0.0004f;   // (0.01*2)^2
    const float C2f = 0.0036f;   // (0.03*2)^2

    const int tid = threadIdx.x;
    const int tx0 = blockIdx.x * TX;
    const int sy0 = blockIdx.y * SY;
    const size_t base = (size_t)blockIdx.z * (size_t)(IMG * IMG);

    float lsum = 0.f;

    #pragma unroll 1
    for (int ch = 0; ch < NCHUNK; ch++) {
        const int y0c = sy0 + ch * TY;   // first output row of this chunk

        if (ch == 0) {
            // ---- full raw load: rows 0..25 <-> gy in [y0c-5, y0c+21) -----
            for (int idx = tid; idx < RROWS * RCOLS; idx += NTHREADS) {
                const int r = idx / RCOLS;
                const int c = idx - r * RCOLS;
                const int gy = y0c + r - 5;
                const int gx = tx0 + c - 5;
                float a = 0.f, b = 0.f;
                if ((unsigned)gy < (unsigned)IMG && (unsigned)gx < (unsigned)IMG) {
                    const size_t o = base + (size_t)gy * IMG + (size_t)gx;
                    a = __ldg(img1 + o);
                    b = __ldg(img2 + o);
                }
                r1[r * RSTRIDE + c] = a;
                r2[r * RSTRIDE + c] = b;
            }
            __syncthreads();

            // ---- stage A, all 26 rows, 8-col runs: 208 jobs --------------
            if (tid < RROWS * 8) {
                const int r  = tid >> 3;
                const int c0 = (tid & 7) * 8;
                const float4* p1 = reinterpret_cast<const float4*>(r1 + r * RSTRIDE + c0);
                const float4* p2 = reinterpret_cast<const float4*>(r2 + r * RSTRIDE + c0);

                float acc[5][8];
                #pragma unroll
                for (int f = 0; f < 5; f++)
                    #pragma unroll
                    for (int i = 0; i < 8; i++) acc[f][i] = 0.f;

                #pragma unroll
                for (int q = 0; q < 5; q++) {
                    const float4 v1 = p1[q];
                    const float4 v2 = p2[q];
                    const float a4[4] = {v1.x, v1.y, v1.z, v1.w};
                    const float b4[4] = {v2.x, v2.y, v2.z, v2.w};
                    #pragma unroll
                    for (int i = 0; i < 4; i++) {
                        const int k = 4 * q + i;
                        if (k < 18) {
                            const float a = a4[i];
                            const float b = b4[i];
                            const float aa = a * a;
                            const float bb = b * b;
                            const float ab = a * b;
                            #pragma unroll
                            for (int jj = 0; jj < 8; jj++) {
                                const int t = k - jj;
                                if (t >= 0 && t <= 10) {
                                    const float w = Wt(t);
                                    acc[0][jj] += w * a;
                                    acc[1][jj] += w * b;
                                    acc[2][jj] += w * aa;
                                    acc[3][jj] += w * bb;
                                    acc[4][jj] += w * ab;
                                }
                            }
                        }
                    }
                }
                #pragma unroll
                for (int f = 0; f < 5; f++) {
                    float* hp = H + (f * RROWS + r) * HSTRIDE + c0;
                    *reinterpret_cast<float4*>(hp) =
                        make_float4(acc[f][0], acc[f][1], acc[f][2], acc[f][3]);
                    *reinterpret_cast<float4*>(hp + 4) =
                        make_float4(acc[f][4], acc[f][5], acc[f][6], acc[f][7]);
                }
            }
            __syncthreads();
        } else {
            __syncthreads();   // prev stage B must finish before H/raw reuse

            // ---- copy H rows 16..25 -> 0..9 (10-row overlap) -------------
            // 10 rows x 16 float4 x 5 fields = 800 float4 jobs.
            for (int idx = tid; idx < 800; idx += NTHREADS) {
                const int f  = idx / 160;
                const int r  = (idx / 16) % 10;
                const int c4 = (idx & 15) * 4;
                const float4 v = *reinterpret_cast<const float4*>(
                    H + (f * RROWS + 16 + r) * HSTRIDE + c4);
                *reinterpret_cast<float4*>(
                    H + (f * RROWS + r) * HSTRIDE + c4) = v;
            }

            // ---- load 16 new raw rows into rows 10..25 -------------------
            // gy in [y0c+5, y0c+21)
            for (int idx = tid; idx < TY * RCOLS; idx += NTHREADS) {
                const int r = idx / RCOLS;        // 0..15
                const int c = idx - r * RCOLS;
                const int gy = y0c + 5 + r;
                const int gx = tx0 + c - 5;
                float a = 0.f, b = 0.f;
                if ((unsigned)gy < (unsigned)IMG && (unsigned)gx < (unsigned)IMG) {
                    const size_t o = base + (size_t)gy * IMG + (size_t)gx;
                    a = __ldg(img1 + o);
                    b = __ldg(img2 + o);
                }
                r1[(10 + r) * RSTRIDE + c] = a;
                r2[(10 + r) * RSTRIDE + c] = b;
            }
            __syncthreads();

            // ---- stage A, 16 new rows, 4-col runs: 256 jobs --------------
            {
                const int r  = 10 + (tid >> 4);       // H/raw row 10..25
                const int c0 = (tid & 15) * 4;
                const float4* p1 = reinterpret_cast<const float4*>(r1 + r * RSTRIDE + c0);
                const float4* p2 = reinterpret_cast<const float4*>(r2 + r * RSTRIDE + c0);

                float acc[5][4];
                #pragma unroll
                for (int f = 0; f < 5; f++)
                    #pragma unroll
                    for (int i = 0; i < 4; i++) acc[f][i] = 0.f;

                #pragma unroll
                for (int q = 0; q < 4; q++) {
                    const float4 v1 = p1[q];
                    const float4 v2 = p2[q];
                    const float a4[4] = {v1.x, v1.y, v1.z, v1.w};
                    const float b4[4] = {v2.x, v2.y, v2.z, v2.w};
                    #pragma unroll
                    for (int i = 0; i < 4; i++) {
                        const int k = 4 * q + i;
                        if (k < 14) {
                            const float a = a4[i];
                            const float b = b4[i];
                            const float aa = a * a;
                            const float bb = b * b;
                            const float ab = a * b;
                            #pragma unroll
                            for (int jj = 0; jj < 4; jj++) {
                                const int t = k - jj;
                                if (t >= 0 && t <= 10) {
                                    const float w = Wt(t);
                                    acc[0][jj] += w * a;
                                    acc[1][jj] += w * b;
                                    acc[2][jj] += w * aa;
                                    acc[3][jj] += w * bb;
                                    acc[4][jj] += w * ab;
                                }
                            }
                        }
                    }
                }
                #pragma unroll
                for (int f = 0; f < 5; f++) {
                    float* hp = H + (f * RROWS + r) * HSTRIDE + c0;
                    *reinterpret_cast<float4*>(hp) =
                        make_float4(acc[f][0], acc[f][1], acc[f][2], acc[f][3]);
                }
            }
            __syncthreads();
        }

        // -------- Stage B: vertical blur + ssim, 4 rows per thread ---------
        {
            const int c  = tid & (TX - 1);        // output column 0..63
            const int g4 = (tid >> 6) * 4;        // first output row in chunk
            float v[5][4];
            #pragma unroll
            for (int f = 0; f < 5; f++)
                #pragma unroll
                for (int i = 0; i < 4; i++) v[f][i] = 0.f;

            #pragma unroll
            for (int k = 0; k < 14; k++) {
                float h[5];
                #pragma unroll
                for (int f = 0; f < 5; f++)
                    h[f] = H[(f * RROWS + g4 + k) * HSTRIDE + c];
                #pragma unroll
                for (int jj = 0; jj < 4; jj++) {
                    const int t = k - jj;
                    if (t >= 0 && t <= 10) {
                        const float w = Wt(t);
                        #pragma unroll
                        for (int f = 0; f < 5; f++) v[f][jj] += w * h[f];
                    }
                }
            }

            #pragma unroll
            for (int jj = 0; jj < 4; jj++) {
                const float mu1 = v[0][jj];
                const float mu2 = v[1][jj];
                const float mu12 = mu1 * mu2;
                const float mu1s = mu1 * mu1;
                const float mu2s = mu2 * mu2;
                const float s1  = v[2][jj] - mu1s;
                const float s2  = v[3][jj] - mu2s;
                const float s12 = v[4][jj] - mu12;
                const float num = (2.f * mu12 + C1f) * (2.f * s12 + C2f);
                const float den = (mu1s + mu2s + C1f) * (s1 + s2 + C2f);
                lsum += __fdividef(num, den);
            }
        }
    }

    // -------- Reduction ----------------------------------------------------
    #pragma unroll
    for (int o = 16; o > 0; o >>= 1)
        lsum += __shfl_xor_sync(0xffffffffu, lsum, o);
    if ((tid & 31) == 0) wsum[tid >> 5] = lsum;
    __syncthreads();
    if (tid == 0) {
        float bs = 0.f;
        #pragma unroll
        for (int w = 0; w < 8; w++) bs += wsum[w];
        atomicAdd(&g_acc, (double)bs);
        __threadfence();
        const unsigned old = atomicAdd(&g_count, 1u);
        if (old == NBLOCKS - 1) {
            const double s = *((volatile double*)&g_acc);
            out[0] = (float)(1.0 - s * (1.0 / 33554432.0));  // 32*1024*1024
            *((volatile double*)&g_acc) = 0.0;
            __threadfence();
            atomicExch(&g_count, 0u);
        }
    }
}

extern "C" void kernel_launch(void* const* d_in, const int* in_sizes, int n_in,
                              void* d_out, int out_size) {
    (void)in_sizes; (void)n_in; (void)out_size;
    const float* img1 = (const float*)d_in[0];
    const float* img2 = (const float*)d_in[1];
    float* out = (float*)d_out;

    static int smem_set = 0;
    if (!smem_set) {
        cudaFuncSetAttribute(ssim_main,
                             cudaFuncAttributeMaxDynamicSharedMemorySize,
                             SMEM_BYTES);
        smem_set = 1;
    }

    dim3 grid(IMG / TX, IMG / SY, 32);   // 16 x 8 x 32 = 4096 blocks
    ssim_main<<<grid, NTHREADS, SMEM_BYTES>>>(img1, img2, out);
}

// round 8
// speedup vs baseline: 1.0497x; 1.0003x over previous
#include <cuda_runtime.h>

// ---------------------------------------------------------------------------
// SSIM loss, fused strip kernel (rolling horizontal-blur buffer).
// Block owns a 64 (x) x 128 (y) strip, processed as 8 chunks of 16 rows.
// Chunk 0: load 26 raw rows, compute all 26 H rows (8-col runs, 208 jobs).
// Chunk i: copy H rows 16..25 -> 0..9 (10-row overlap carried), load 16 new
//          raw rows, compute 16 new H rows (4-col runs, 256 jobs = 256 thr).
// Stage B per chunk: vertical 11-tap blur + ssim epilogue, 4-row runs.
//          The 4 ssim fractions are combined rationally (n1/d1 + n2/d2 =
//          (n1 d2 + n2 d1)/(d1 d2)) so each thread does ONE __fdividef per
//          chunk instead of four: MUFU.RCP was the chip-wide bottleneck
//          (rt 8 cyc/SMSP -> 0.5/cyc/SM; 1 rcp/px == ~300 us by itself).
// H layout: 5 scalar planes [RROWS][HSTRIDE] (conflict-free stage-B LDS).
// Weights are compile-time immediates -> FFMA-imm (rt_SMSP=1).
// Reduce: warp shuffle -> block -> atomicAdd(double); counter-elected last
//         block writes 1 - mean and resets accumulators (replay-safe).
// ---------------------------------------------------------------------------

#define NTHREADS 256
#define TX 64
#define TY 16            // rows per chunk
#define NCHUNK 8         // chunks per strip
#define SY (TY * NCHUNK) // 128 rows per strip
#define RROWS 26         // TY + 10
#define RCOLS 74         // TX + 10
#define RSTRIDE 76       // raw row stride (floats), multiple of 4
#define HSTRIDE 68       // H row stride (floats), multiple of 4
#define IMG 1024
#define NBLOCKS (16 * 8 * 32)

#define SMEM_FLOATS (2 * RROWS * RSTRIDE + 5 * RROWS * HSTRIDE + 8)
#define SMEM_BYTES (SMEM_FLOATS * 4)   // 51,232 B -> 4 blocks/SM

static __device__ __forceinline__ float Wt(int t) {
    // Gaussian, WIN=11, SIGMA=1.5, normalized; compile-time constants so
    // ptxas emits FFMA-imm (rt_SMSP=1, 2x tput vs 3-reg FFMA).
    constexpr float w[6] = {0.00102838f, 0.00759875f, 0.03600077f,
                            0.10936069f, 0.21300553f, 0.26601172f};
    return (t < 6) ? w[t] : w[10 - t];
}

__device__ double g_acc = 0.0;
__device__ unsigned g_count = 0u;

__global__ __launch_bounds__(NTHREADS, 4)
void ssim_main(const float* __restrict__ img1, const float* __restrict__ img2,
               float* __restrict__ out) {
    extern __shared__ float smem[];
    float* r1   = smem;                                // [RROWS][RSTRIDE]
    float* r2   = smem + RROWS * RSTRIDE;              // [RROWS][RSTRIDE]
    float* H    = smem + 2 * RROWS * RSTRIDE;          // [5][RROWS][HSTRIDE]
    float* wsum = H + 5 * RROWS * HSTRIDE;             // [8]

    const float C1f = 0.0004f;   // (0.01*2)^2
    const float C2f = 0.0036f;   // (0.03*2)^2

    const int tid = threadIdx.x;
    const int tx0 = blockIdx.x * TX;
    const int sy0 = blockIdx.y * SY;
    const size_t base = (size_t)blockIdx.z * (size_t)(IMG * IMG);

    float lsum = 0.f;

    #pragma unroll 1
    for (int ch = 0; ch < NCHUNK; ch++) {
        const int y0c = sy0 + ch * TY;   // first output row of this chunk

        if (ch == 0) {
            // ---- full raw load: rows 0..25 <-> gy in [y0c-5, y0c+21) -----
            for (int idx = tid; idx < RROWS * RCOLS; idx += NTHREADS) {
                const int r = idx / RCOLS;
                const int c = idx - r * RCOLS;
                const int gy = y0c + r - 5;
                const int gx = tx0 + c - 5;
                float a = 0.f, b = 0.f;
                if ((unsigned)gy < (unsigned)IMG && (unsigned)gx < (unsigned)IMG) {
                    const size_t o = base + (size_t)gy * IMG + (size_t)gx;
                    a = __ldg(img1 + o);
                    b = __ldg(img2 + o);
                }
                r1[r * RSTRIDE + c] = a;
                r2[r * RSTRIDE + c] = b;
            }
            __syncthreads();

            // ---- stage A, all 26 rows, 8-col runs: 208 jobs --------------
            if (tid < RROWS * 8) {
                const int r  = tid >> 3;
                const int c0 = (tid & 7) * 8;
                const float4* p1 = reinterpret_cast<const float4*>(r1 + r * RSTRIDE + c0);
                const float4* p2 = reinterpret_cast<const float4*>(r2 + r * RSTRIDE + c0);

                float acc[5][8];
                #pragma unroll
                for (int f = 0; f < 5; f++)
                    #pragma unroll
                    for (int i = 0; i < 8; i++) acc[f][i] = 0.f;

                #pragma unroll
                for (int q = 0; q < 5; q++) {
                    const float4 v1 = p1[q];
                    const float4 v2 = p2[q];
                    const float a4[4] = {v1.x, v1.y, v1.z, v1.w};
                    const float b4[4] = {v2.x, v2.y, v2.z, v2.w};
                    #pragma unroll
                    for (int i = 0; i < 4; i++) {
                        const int k = 4 * q + i;
                        if (k < 18) {
                            const float a = a4[i];
                            const float b = b4[i];
                            const float aa = a * a;
                            const float bb = b * b;
                            const float ab = a * b;
                            #pragma unroll
                            for (int jj = 0; jj < 8; jj++) {
                                const int t = k - jj;
                                if (t >= 0 && t <= 10) {
                                    const float w = Wt(t);
                                    acc[0][jj] += w * a;
                                    acc[1][jj] += w * b;
                                    acc[2][jj] += w * aa;
                                    acc[3][jj] += w * bb;
                                    acc[4][jj] += w * ab;
                                }
                            }
                        }
                    }
                }
                #pragma unroll
                for (int f = 0; f < 5; f++) {
                    float* hp = H + (f * RROWS + r) * HSTRIDE + c0;
                    *reinterpret_cast<float4*>(hp) =
                        make_float4(acc[f][0], acc[f][1], acc[f][2], acc[f][3]);
                    *reinterpret_cast<float4*>(hp + 4) =
                        make_float4(acc[f][4], acc[f][5], acc[f][6], acc[f][7]);
                }
            }
            __syncthreads();
        } else {
            __syncthreads();   // prev stage B must finish before H/raw reuse

            // ---- copy H rows 16..25 -> 0..9 (10-row overlap) -------------
            // 10 rows x 16 float4 x 5 fields = 800 float4 jobs.
            for (int idx = tid; idx < 800; idx += NTHREADS) {
                const int f  = idx / 160;
                const int r  = (idx / 16) % 10;
                const int c4 = (idx & 15) * 4;
                const float4 v = *reinterpret_cast<const float4*>(
                    H + (f * RROWS + 16 + r) * HSTRIDE + c4);
                *reinterpret_cast<float4*>(
                    H + (f * RROWS + r) * HSTRIDE + c4) = v;
            }

            // ---- load 16 new raw rows into rows 10..25 -------------------
            // gy in [y0c+5, y0c+21)
            for (int idx = tid; idx < TY * RCOLS; idx += NTHREADS) {
                const int r = idx / RCOLS;        // 0..15
                const int c = idx - r * RCOLS;
                const int gy = y0c + 5 + r;
                const int gx = tx0 + c - 5;
                float a = 0.f, b = 0.f;
                if ((unsigned)gy < (unsigned)IMG && (unsigned)gx < (unsigned)IMG) {
                    const size_t o = base + (size_t)gy * IMG + (size_t)gx;
                    a = __ldg(img1 + o);
                    b = __ldg(img2 + o);
                }
                r1[(10 + r) * RSTRIDE + c] = a;
                r2[(10 + r) * RSTRIDE + c] = b;
            }
            __syncthreads();

            // ---- stage A, 16 new rows, 4-col runs: 256 jobs --------------
            {
                const int r  = 10 + (tid >> 4);       // H/raw row 10..25
                const int c0 = (tid & 15) * 4;
                const float4* p1 = reinterpret_cast<const float4*>(r1 + r * RSTRIDE + c0);
                const float4* p2 = reinterpret_cast<const float4*>(r2 + r * RSTRIDE + c0);

                float acc[5][4];
                #pragma unroll
                for (int f = 0; f < 5; f++)
                    #pragma unroll
                    for (int i = 0; i < 4; i++) acc[f][i] = 0.f;

                #pragma unroll
                for (int q = 0; q < 4; q++) {
                    const float4 v1 = p1[q];
                    const float4 v2 = p2[q];
                    const float a4[4] = {v1.x, v1.y, v1.z, v1.w};
                    const float b4[4] = {v2.x, v2.y, v2.z, v2.w};
                    #pragma unroll
                    for (int i = 0; i < 4; i++) {
                        const int k = 4 * q + i;
                        if (k < 14) {
                            const float a = a4[i];
                            const float b = b4[i];
                            const float aa = a * a;
                            const float bb = b * b;
                            const float ab = a * b;
                            #pragma unroll
                            for (int jj = 0; jj < 4; jj++) {
                                const int t = k - jj;
                                if (t >= 0 && t <= 10) {
                                    const float w = Wt(t);
                                    acc[0][jj] += w * a;
                                    acc[1][jj] += w * b;
                                    acc[2][jj] += w * aa;
                                    acc[3][jj] += w * bb;
                                    acc[4][jj] += w * ab;
                                }
                            }
                        }
                    }
                }
                #pragma unroll
                for (int f = 0; f < 5; f++) {
                    float* hp = H + (f * RROWS + r) * HSTRIDE + c0;
                    *reinterpret_cast<float4*>(hp) =
                        make_float4(acc[f][0], acc[f][1], acc[f][2], acc[f][3]);
                }
            }
            __syncthreads();
        }

        // -------- Stage B: vertical blur + ssim, 4 rows per thread ---------
        {
            const int c  = tid & (TX - 1);        // output column 0..63
            const int g4 = (tid >> 6) * 4;        // first output row in chunk
            float v[5][4];
            #pragma unroll
            for (int f = 0; f < 5; f++)
                #pragma unroll
                for (int i = 0; i < 4; i++) v[f][i] = 0.f;

            #pragma unroll
            for (int k = 0; k < 14; k++) {
                float h[5];
                #pragma unroll
                for (int f = 0; f < 5; f++)
                    h[f] = H[(f * RROWS + g4 + k) * HSTRIDE + c];
                #pragma unroll
                for (int jj = 0; jj < 4; jj++) {
                    const int t = k - jj;
                    if (t >= 0 && t <= 10) {
                        const float w = Wt(t);
                        #pragma unroll
                        for (int f = 0; f < 5; f++) v[f][jj] += w * h[f];
                    }
                }
            }

            // ssim fractions; combine 4 rationally -> ONE divide per chunk.
            float Nn[4], Dd[4];
            #pragma unroll
            for (int jj = 0; jj < 4; jj++) {
                const float mu1 = v[0][jj];
                const float mu2 = v[1][jj];
                const float mu12 = mu1 * mu2;
                const float mu1s = mu1 * mu1;
                const float mu2s = mu2 * mu2;
                const float s1  = v[2][jj] - mu1s;
                const float s2  = v[3][jj] - mu2s;
                const float s12 = v[4][jj] - mu12;
                Nn[jj] = (2.f * mu12 + C1f) * (2.f * s12 + C2f);
                Dd[jj] = (mu1s + mu2s + C1f) * (s1 + s2 + C2f);
            }
            const float n01 = Nn[0] * Dd[1] + Nn[1] * Dd[0];
            const float d01 = Dd[0] * Dd[1];
            const float n23 = Nn[2] * Dd[3] + Nn[3] * Dd[2];
            const float d23 = Dd[2] * Dd[3];
            lsum += __fdividef(n01 * d23 + n23 * d01, d01 * d23);
        }
    }

    // -------- Reduction ----------------------------------------------------
    #pragma unroll
    for (int o = 16; o > 0; o >>= 1)
        lsum += __shfl_xor_sync(0xffffffffu, lsum, o);
    if ((tid & 31) == 0) wsum[tid >> 5] = lsum;
    __syncthreads();
    if (tid == 0) {
        float bs = 0.f;
        #pragma unroll
        for (int w = 0; w < 8; w++) bs += wsum[w];
        atomicAdd(&g_acc, (double)bs);
        __threadfence();
        const unsigned old = atomicAdd(&g_count, 1u);
        if (old == NBLOCKS - 1) {
            const double s = *((volatile double*)&g_acc);
            out[0] = (float)(1.0 - s * (1.0 / 33554432.0));  // 32*1024*1024
            *((volatile double*)&g_acc) = 0.0;
            __threadfence();
            atomicExch(&g_count, 0u);
        }
    }
}

extern "C" void kernel_launch(void* const* d_in, const int* in_sizes, int n_in,
                              void* d_out, int out_size) {
    (void)in_sizes; (void)n_in; (void)out_size;
    const float* img1 = (const float*)d_in[0];
    const float* img2 = (const float*)d_in[1];
    float* out = (float*)d_out;

    static int smem_set = 0;
    if (!smem_set) {
        cudaFuncSetAttribute(ssim_main,
                             cudaFuncAttributeMaxDynamicSharedMemorySize,
                             SMEM_BYTES);
        smem_set = 1;
    }

    dim3 grid(IMG / TX, IMG / SY, 32);   // 16 x 8 x 32 = 4096 blocks
    ssim_main<<<grid, NTHREADS, SMEM_BYTES>>>(img1, img2, out);
}

// round 9
// speedup vs baseline: 1.2053x; 1.1483x over previous
#include <cuda_runtime.h>

// ---------------------------------------------------------------------------
// SSIM loss, fused strip kernel (rolling horizontal-blur buffer),
// vectorized float4 global loads, div-free-ish loader indexing.
// Block owns a 64 (x) x 128 (y) strip, processed as 8 chunks of 16 rows.
// Raw buffer covers gx in [tx0-8, tx0+72): 80 cols -> aligned float4 LDG;
// interior blocks skip x-bounds checks entirely (uniform branch).
// Chunk 0: load 26 raw rows, compute all 26 H rows (8-col runs, 208 jobs).
// Chunk i: copy H rows 16..25 -> 0..9, load 16 new raw rows, compute 16 new
//          H rows (4-col runs, 256 jobs = 256 threads).
// Stage B per chunk: vertical 11-tap blur + ssim epilogue, 4-row runs; the 4
//          ssim fractions combine rationally -> ONE __fdividef per chunk.
// Weights are compile-time immediates -> FFMA-imm (rt_SMSP=1).
// Reduce: warp shuffle -> block -> atomicAdd(double); counter-elected last
//         block writes 1 - mean and resets accumulators (replay-safe).
// ---------------------------------------------------------------------------

#define NTHREADS 256
#define TX 64
#define TY 16            // rows per chunk
#define NCHUNK 8         // chunks per strip
#define SY (TY * NCHUNK) // 128 rows per strip
#define RROWS 26         // TY + 10
#define RSTRIDE 80       // raw cols: gx in [tx0-8, tx0+72), float4-aligned
#define HSTRIDE 68       // H row stride (floats), multiple of 4
#define IMG 1024
#define NBLOCKS (16 * 8 * 32)

#define SMEM_FLOATS (2 * RROWS * RSTRIDE + 5 * RROWS * HSTRIDE + 8)
#define SMEM_BYTES (SMEM_FLOATS * 4)   // 52,032 B -> 4 blocks/SM

static __device__ __forceinline__ float Wt(int t) {
    // Gaussian, WIN=11, SIGMA=1.5, normalized; compile-time constants so
    // ptxas emits FFMA-imm (rt_SMSP=1, 2x tput vs 3-reg FFMA).
    constexpr float w[6] = {0.00102838f, 0.00759875f, 0.03600077f,
                            0.10936069f, 0.21300553f, 0.26601172f};
    return (t < 6) ? w[t] : w[10 - t];
}

__device__ double g_acc = 0.0;
__device__ unsigned g_count = 0u;

__global__ __launch_bounds__(NTHREADS, 4)
void ssim_main(const float* __restrict__ img1, const float* __restrict__ img2,
               float* __restrict__ out) {
    extern __shared__ float smem[];
    float* r1   = smem;                                // [RROWS][RSTRIDE]
    float* r2   = smem + RROWS * RSTRIDE;              // [RROWS][RSTRIDE]
    float* H    = smem + 2 * RROWS * RSTRIDE;          // [5][RROWS][HSTRIDE]
    float* wsum = H + 5 * RROWS * HSTRIDE;             // [8]

    const float C1f = 0.0004f;   // (0.01*2)^2
    const float C2f = 0.0036f;   // (0.03*2)^2

    const int tid = threadIdx.x;
    const int tx0 = blockIdx.x * TX;
    const int sy0 = blockIdx.y * SY;
    const size_t base = (size_t)blockIdx.z * (size_t)(IMG * IMG);
    const bool xedge = (blockIdx.x == 0) | (blockIdx.x == (IMG / TX - 1));

    float lsum = 0.f;

    #pragma unroll 1
    for (int ch = 0; ch < NCHUNK; ch++) {
        const int y0c = sy0 + ch * TY;   // first output row of this chunk

        if (ch == 0) {
            // ---- full raw load: rows 0..25 <-> gy in [y0c-5, y0c+21) -----
            if (!xedge) {
                // fast path: aligned float4, no x checks. 26*20 = 520 jobs.
                for (int idx = tid; idx < RROWS * 20; idx += NTHREADS) {
                    const int r = idx / 20;
                    const int q = idx - r * 20;
                    const int gy = y0c + r - 5;
                    float4 a = make_float4(0.f, 0.f, 0.f, 0.f), b = a;
                    if ((unsigned)gy < (unsigned)IMG) {
                        const size_t o = base + (size_t)gy * IMG + (tx0 - 8 + 4 * q);
                        a = *reinterpret_cast<const float4*>(img1 + o);
                        b = *reinterpret_cast<const float4*>(img2 + o);
                    }
                    *reinterpret_cast<float4*>(r1 + r * RSTRIDE + 4 * q) = a;
                    *reinterpret_cast<float4*>(r2 + r * RSTRIDE + 4 * q) = b;
                }
            } else {
                for (int idx = tid; idx < RROWS * RSTRIDE; idx += NTHREADS) {
                    const int r = idx / RSTRIDE;
                    const int c = idx - r * RSTRIDE;
                    const int gy = y0c + r - 5;
                    const int gx = tx0 - 8 + c;
                    float a = 0.f, b = 0.f;
                    if ((unsigned)gy < (unsigned)IMG && (unsigned)gx < (unsigned)IMG) {
                        const size_t o = base + (size_t)gy * IMG + (size_t)gx;
                        a = __ldg(img1 + o);
                        b = __ldg(img2 + o);
                    }
                    r1[r * RSTRIDE + c] = a;
                    r2[r * RSTRIDE + c] = b;
                }
            }
            __syncthreads();

            // ---- stage A, all 26 rows, 8-col runs: 208 jobs --------------
            // Output col j (0..63) taps buffer cols j+3 .. j+13.
            if (tid < RROWS * 8) {
                const int r  = tid >> 3;
                const int c0 = (tid & 7) * 8;
                const float4* p1 = reinterpret_cast<const float4*>(r1 + r * RSTRIDE + c0);
                const float4* p2 = reinterpret_cast<const float4*>(r2 + r * RSTRIDE + c0);

                float acc[5][8];
                #pragma unroll
                for (int f = 0; f < 5; f++)
                    #pragma unroll
                    for (int i = 0; i < 8; i++) acc[f][i] = 0.f;

                #pragma unroll
                for (int q = 0; q < 6; q++) {
                    const float4 v1 = p1[q];
                    const float4 v2 = p2[q];
                    const float a4[4] = {v1.x, v1.y, v1.z, v1.w};
                    const float b4[4] = {v2.x, v2.y, v2.z, v2.w};
                    #pragma unroll
                    for (int i = 0; i < 4; i++) {
                        const int k = 4 * q + i - 3;   // tap window index
                        if (k >= 0 && k < 18) {
                            const float a = a4[i];
                            const float b = b4[i];
                            const float aa = a * a;
                            const float bb = b * b;
                            const float ab = a * b;
                            #pragma unroll
                            for (int jj = 0; jj < 8; jj++) {
                                const int t = k - jj;
                                if (t >= 0 && t <= 10) {
                                    const float w = Wt(t);
                                    acc[0][jj] += w * a;
                                    acc[1][jj] += w * b;
                                    acc[2][jj] += w * aa;
                                    acc[3][jj] += w * bb;
                                    acc[4][jj] += w * ab;
                                }
                            }
                        }
                    }
                }
                #pragma unroll
                for (int f = 0; f < 5; f++) {
                    float* hp = H + (f * RROWS + r) * HSTRIDE + c0;
                    *reinterpret_cast<float4*>(hp) =
                        make_float4(acc[f][0], acc[f][1], acc[f][2], acc[f][3]);
                    *reinterpret_cast<float4*>(hp + 4) =
                        make_float4(acc[f][4], acc[f][5], acc[f][6], acc[f][7]);
                }
            }
            __syncthreads();
        } else {
            __syncthreads();   // prev stage B must finish before H/raw reuse

            // ---- copy H rows 16..25 -> 0..9 (10-row overlap) -------------
            for (int idx = tid; idx < 800; idx += NTHREADS) {
                const int f  = idx / 160;
                const int r  = (idx / 16) % 10;
                const int c4 = (idx & 15) * 4;
                const float4 v = *reinterpret_cast<const float4*>(
                    H + (f * RROWS + 16 + r) * HSTRIDE + c4);
                *reinterpret_cast<float4*>(
                    H + (f * RROWS + r) * HSTRIDE + c4) = v;
            }

            // ---- load 16 new raw rows into rows 10..25 -------------------
            // gy in [y0c+5, y0c+21)
            if (!xedge) {
                // 16*20 = 320 float4-pair jobs.
                for (int idx = tid; idx < TY * 20; idx += NTHREADS) {
                    const int r = idx / 20;
                    const int q = idx - r * 20;
                    const int gy = y0c + 5 + r;
                    float4 a = make_float4(0.f, 0.f, 0.f, 0.f), b = a;
                    if ((unsigned)gy < (unsigned)IMG) {
                        const size_t o = base + (size_t)gy * IMG + (tx0 - 8 + 4 * q);
                        a = *reinterpret_cast<const float4*>(img1 + o);
                        b = *reinterpret_cast<const float4*>(img2 + o);
                    }
                    *reinterpret_cast<float4*>(r1 + (10 + r) * RSTRIDE + 4 * q) = a;
                    *reinterpret_cast<float4*>(r2 + (10 + r) * RSTRIDE + 4 * q) = b;
                }
            } else {
                for (int idx = tid; idx < TY * RSTRIDE; idx += NTHREADS) {
                    const int r = idx / RSTRIDE;
                    const int c = idx - r * RSTRIDE;
                    const int gy = y0c + 5 + r;
                    const int gx = tx0 - 8 + c;
                    float a = 0.f, b = 0.f;
                    if ((unsigned)gy < (unsigned)IMG && (unsigned)gx < (unsigned)IMG) {
                        const size_t o = base + (size_t)gy * IMG + (size_t)gx;
                        a = __ldg(img1 + o);
                        b = __ldg(img2 + o);
                    }
                    r1[(10 + r) * RSTRIDE + c] = a;
                    r2[(10 + r) * RSTRIDE + c] = b;
                }
            }
            __syncthreads();

            // ---- stage A, 16 new rows, 4-col runs: 256 jobs --------------
            // Output col j needs buffer cols j+3 .. j+13.
            {
                const int r  = 10 + (tid >> 4);       // H/raw row 10..25
                const int c0 = (tid & 15) * 4;
                const float4* p1 = reinterpret_cast<const float4*>(r1 + r * RSTRIDE + c0);
                const float4* p2 = reinterpret_cast<const float4*>(r2 + r * RSTRIDE + c0);

                float acc[5][4];
                #pragma unroll
                for (int f = 0; f < 5; f++)
                    #pragma unroll
                    for (int i = 0; i < 4; i++) acc[f][i] = 0.f;

                #pragma unroll
                for (int q = 0; q < 5; q++) {
                    const float4 v1 = p1[q];
                    const float4 v2 = p2[q];
                    const float a4[4] = {v1.x, v1.y, v1.z, v1.w};
                    const float b4[4] = {v2.x, v2.y, v2.z, v2.w};
                    #pragma unroll
                    for (int i = 0; i < 4; i++) {
                        const int k = 4 * q + i - 3;   // tap window index
                        if (k >= 0 && k < 14) {
                            const float a = a4[i];
                            const float b = b4[i];
                            const float aa = a * a;
                            const float bb = b * b;
                            const float ab = a * b;
                            #pragma unroll
                            for (int jj = 0; jj < 4; jj++) {
                                const int t = k - jj;
                                if (t >= 0 && t <= 10) {
                                    const float w = Wt(t);
                                    acc[0][jj] += w * a;
                                    acc[1][jj] += w * b;
                                    acc[2][jj] += w * aa;
                                    acc[3][jj] += w * bb;
                                    acc[4][jj] += w * ab;
                                }
                            }
                        }
                    }
                }
                #pragma unroll
                for (int f = 0; f < 5; f++) {
                    float* hp = H + (f * RROWS + r) * HSTRIDE + c0;
                    *reinterpret_cast<float4*>(hp) =
                        make_float4(acc[f][0], acc[f][1], acc[f][2], acc[f][3]);
                }
            }
            __syncthreads();
        }

        // -------- Stage B: vertical blur + ssim, 4 rows per thread ---------
        {
            const int c  = tid & (TX - 1);        // output column 0..63
            const int g4 = (tid >> 6) * 4;        // first output row in chunk
            float v[5][4];
            #pragma unroll
            for (int f = 0; f < 5; f++)
                #pragma unroll
                for (int i = 0; i < 4; i++) v[f][i] = 0.f;

            #pragma unroll
            for (int k = 0; k < 14; k++) {
                float h[5];
                #pragma unroll
                for (int f = 0; f < 5; f++)
                    h[f] = H[(f * RROWS + g4 + k) * HSTRIDE + c];
                #pragma unroll
                for (int jj = 0; jj < 4; jj++) {
                    const int t = k - jj;
                    if (t >= 0 && t <= 10) {
                        const float w = Wt(t);
                        #pragma unroll
                        for (int f = 0; f < 5; f++) v[f][jj] += w * h[f];
                    }
                }
            }

            // ssim fractions; combine 4 rationally -> ONE divide per chunk.
            float Nn[4], Dd[4];
            #pragma unroll
            for (int jj = 0; jj < 4; jj++) {
                const float mu1 = v[0][jj];
                const float mu2 = v[1][jj];
                const float mu12 = mu1 * mu2;
                const float mu1s = mu1 * mu1;
                const float mu2s = mu2 * mu2;
                const float s1  = v[2][jj] - mu1s;
                const float s2  = v[3][jj] - mu2s;
                const float s12 = v[4][jj] - mu12;
                Nn[jj] = (2.f * mu12 + C1f) * (2.f * s12 + C2f);
                Dd[jj] = (mu1s + mu2s + C1f) * (s1 + s2 + C2f);
            }
            const float n01 = Nn[0] * Dd[1] + Nn[1] * Dd[0];
            const float d01 = Dd[0] * Dd[1];
            const float n23 = Nn[2] * Dd[3] + Nn[3] * Dd[2];
            const float d23 = Dd[2] * Dd[3];
            lsum += __fdividef(n01 * d23 + n23 * d01, d01 * d23);
        }
    }

    // -------- Reduction ----------------------------------------------------
    #pragma unroll
    for (int o = 16; o > 0; o >>= 1)
        lsum += __shfl_xor_sync(0xffffffffu, lsum, o);
    if ((tid & 31) == 0) wsum[tid >> 5] = lsum;
    __syncthreads();
    if (tid == 0) {
        float bs = 0.f;
        #pragma unroll
        for (int w = 0; w < 8; w++) bs += wsum[w];
        atomicAdd(&g_acc, (double)bs);
        __threadfence();
        const unsigned old = atomicAdd(&g_count, 1u);
        if (old == NBLOCKS - 1) {
            const double s = *((volatile double*)&g_acc);
            out[0] = (float)(1.0 - s * (1.0 / 33554432.0));  // 32*1024*1024
            *((volatile double*)&g_acc) = 0.0;
            __threadfence();
            atomicExch(&g_count, 0u);
        }
    }
}

extern "C" void kernel_launch(void* const* d_in, const int* in_sizes, int n_in,
                              void* d_out, int out_size) {
    (void)in_sizes; (void)n_in; (void)out_size;
    const float* img1 = (const float*)d_in[0];
    const float* img2 = (const float*)d_in[1];
    float* out = (float*)d_out;

    static int smem_set = 0;
    if (!smem_set) {
        cudaFuncSetAttribute(ssim_main,
                             cudaFuncAttributeMaxDynamicSharedMemorySize,
                             SMEM_BYTES);
        smem_set = 1;
    }

    dim3 grid(IMG / TX, IMG / SY, 32);   // 16 x 8 x 32 = 4096 blocks
    ssim_main<<<grid, NTHREADS, SMEM_BYTES>>>(img1, img2, out);
}